// round 11
// baseline (speedup 1.0000x reference)
#include <cuda_runtime.h>
#include <cuda_fp16.h>
#include <cstdint>

#define BB 8
#define LL 2048
#define VV 8192
#define CC 64
#define NQ (BB * LL)
#define NVH 8
#define VH (VV / NVH)        // 1024 verts per CTA
#define NCH (VH / 64)        // 16 chunks of 64 verts
#define NCG (VV / 64)        // 128 chunks globally
#define RX 136

static __device__ float  g_part[(size_t)NQ * NVH * RX];     // [q][vh][136]
static __device__ float4 g_vn[2 * BB * VV];                  // (-2x,-2y,-2z,|v|^2)
static __device__ uint2  g_fB[(size_t)2 * BB * NCG * 1024];  // frag-major fp16 B tiles (t-paired)
static __device__ float  g_w1t[132 * 132];
static __device__ float  g_b1p[132];
static __device__ float  g_w2p[132];

__device__ __forceinline__ void cp16(uint32_t d, const void* s) {
    asm volatile("cp.async.cg.shared.global [%0], [%1], 16;" :: "r"(d), "l"(s));
}
__device__ __forceinline__ uint4 lds128(uint32_t addr) {
    uint4 r;
    asm volatile("ld.shared.v4.b32 {%0,%1,%2,%3}, [%4];"
                 : "=r"(r.x), "=r"(r.y), "=r"(r.z), "=r"(r.w) : "r"(addr));
    return r;
}
__device__ __forceinline__ uint32_t packh2(float lo, float hi) {
    uint32_t r;
    asm("cvt.rn.f16x2.f32 %0, %1, %2;" : "=r"(r) : "f"(hi), "f"(lo));
    return r;
}
__device__ __forceinline__ uint32_t ex2h2(uint32_t a) {
    uint32_t r;
    asm("ex2.approx.f16x2 %0, %1;" : "=r"(r) : "r"(a));
    return r;
}
// w pair from two fp32 squared distances: clamp->rsqrt->d->*(-log2e/sigma)->2^x
__device__ __forceinline__ uint32_t wpair(float d2a, float d2b) {
    const __half2 minn = __halves2half2(__ushort_as_half(0x0400), __ushort_as_half(0x0400));
    const __half2 negc = __float2half2_rn(-0.57707801635558535f);
    uint32_t u = packh2(d2a, d2b);
    __half2 v = __hmax2(*(__half2*)&u, minn);
    __half2 r = h2rsqrt(v);
    __half2 d = __hmul2(v, r);
    __half2 a = __hmul2(d, negc);
    return ex2h2(*(uint32_t*)&a);
}
__device__ __forceinline__ void mma16816(float* d, uint32_t a0, uint32_t a1, uint32_t a2,
                                         uint32_t a3, uint32_t b0, uint32_t b1) {
    asm volatile(
        "mma.sync.aligned.m16n8k16.row.col.f32.f16.f16.f32 "
        "{%0,%1,%2,%3},{%4,%5,%6,%7},{%8,%9},{%0,%1,%2,%3};"
        : "+f"(d[0]), "+f"(d[1]), "+f"(d[2]), "+f"(d[3])
        : "r"(a0), "r"(a1), "r"(a2), "r"(a3), "r"(b0), "r"(b1));
}

// ---------------- preps ----------------
__global__ void prep_vn_kernel(const float* __restrict__ vL, const float* __restrict__ vR) {
    const int v = blockIdx.x * 256 + threadIdx.x;
    const int bs = blockIdx.y, b = bs >> 1, side = bs & 1;
    const float* vp = (side ? vR : vL) + ((size_t)b * VV + v) * 3;
    const float x = vp[0], y = vp[1], z = vp[2];
    g_vn[(size_t)bs * VV + v] =
        make_float4(-2.f * x, -2.f * y, -2.f * z, fmaf(x, x, fmaf(y, y, z * z)));
}

// fragment-major, t-paired B: group (kk, tp) holds t=2tp (.x.y) and t=2tp+1 (.z.w)
//   c = t*8 + (lane>>2);  v = ci*64 + kk*16 + (lane&3)*4 + {0..3}
__global__ void prep_feats_kernel(const float* __restrict__ fL, const float* __restrict__ fR) {
    __shared__ float tile[64][65];
    const int ci = blockIdx.x, bs = blockIdx.y, b = bs >> 1, side = bs & 1;
    const int tid = threadIdx.x;
    const float* src = (side ? fR : fL) + ((size_t)b * VV + (size_t)ci * 64) * CC;
#pragma unroll
    for (int i = 0; i < 16; i++) {
        int idx = tid + 256 * i;
        tile[idx >> 6][idx & 63] = src[idx];   // tile[v][c]
    }
    __syncthreads();
    uint2* dst = g_fB + ((size_t)bs * NCG + ci) * 1024;
#pragma unroll
    for (int i = 0; i < 4; i++) {
        int idx = tid + 256 * i;               // (kk*8+t)*32+lane
        int lane = idx & 31, t = (idx >> 5) & 7, kk = idx >> 8;
        int c = t * 8 + (lane >> 2);
        int v0 = kk * 16 + (lane & 3) * 4;
        __half2 p0 = __floats2half2_rn(tile[v0 + 0][c], tile[v0 + 1][c]);
        __half2 p1 = __floats2half2_rn(tile[v0 + 2][c], tile[v0 + 3][c]);
        uint2 o; o.x = *(uint32_t*)&p0; o.y = *(uint32_t*)&p1;
        dst[(kk * 4 + (t >> 1)) * 64 + lane * 2 + (t & 1)] = o;
    }
}

__global__ void prep_w1_kernel(const float* __restrict__ w1, const float* __restrict__ b1,
                               const float* __restrict__ w2) {
    const int idx = blockIdx.x * 256 + threadIdx.x;
    if (idx < 132 * 132) {
        const int k = idx / 132, j = idx % 132;
        g_w1t[idx] = (j < 130 && k < 130) ? w1[j * 130 + k] : 0.f;
    }
    if (blockIdx.x == 0 && idx < 132) {
        g_b1p[idx] = (idx < 130) ? b1[idx] : 0.f;
        g_w2p[idx] = (idx < 130) ? w2[idx] : 0.f;
    }
}

// ---------------- fused interp ----------------
// grid (LL/128, 16, NVH), block 128 (4 warps, each M=32 x N=65)
// stage: B frags @0 (8192B), vn @8192 (1024B)
#define STG 9216

__global__ void __launch_bounds__(128, 4)
interp_kernel(const float* __restrict__ locsL, const float* __restrict__ locsR) {
    __shared__ __align__(1024) char smem[2 * STG];
    const uint32_t sb = (uint32_t)__cvta_generic_to_shared(smem);
    const int tid = threadIdx.x, lane = tid & 31, warp = tid >> 5;
    const int lt = blockIdx.x, bs = blockIdx.y, vh = blockIdx.z;
    const int b = bs >> 1, side = bs & 1;

    const float* locs = (side ? locsR : locsL) + (size_t)b * LL * 3;
    float px[4], py[4], pz[4], n2[4];
    const int rbase = lt * 128 + warp * 32 + (lane >> 2);
#pragma unroll
    for (int ri = 0; ri < 4; ri++) {
        const float* p = locs + (size_t)(rbase + ri * 8) * 3;
        px[ri] = p[0]; py[ri] = p[1]; pz[ri] = p[2];
        n2[ri] = fmaf(px[ri], px[ri], fmaf(py[ri], py[ri], pz[ri] * pz[ri]));
    }
    const uint2*  fbb = g_fB + ((size_t)bs * NCG + vh * NCH) * 1024;
    const float4* vnb = g_vn + (size_t)bs * VV + vh * VH;

    // t=8 constant B fragment (dens column: channel 64 = ones, 65..71 zero)
    const uint32_t bcst = ((lane >> 2) == 0) ? 0x3C003C00u : 0u;

    float acc[2][9][4];
#pragma unroll
    for (int m = 0; m < 2; m++)
#pragma unroll
        for (int t = 0; t < 9; t++)
#pragma unroll
            for (int i = 0; i < 4; i++) acc[m][t][i] = 0.f;

    auto stage_cp = [&](int ch) {
        const uint32_t dst = sb + (uint32_t)(ch & 1) * STG;
        const char* src = (const char*)(fbb + (size_t)ch * 1024);
#pragma unroll
        for (int i = 0; i < 4; i++)
            cp16(dst + (tid + i * 128) * 16, src + (tid + i * 128) * 16);
        if (tid < 64) cp16(dst + 8192 + tid * 16, vnb + ch * 64 + tid);
        asm volatile("cp.async.commit_group;");
    };

    stage_cp(0);
    stage_cp(1);

    const int q = lane & 3;

    for (int ch = 0; ch < NCH; ch++) {
        const int s = ch & 1;
        if (ch == NCH - 1) asm volatile("cp.async.wait_group 0;");
        else               asm volatile("cp.async.wait_group 1;");
        __syncthreads();

        const uint32_t lb = sb + (uint32_t)s * STG + (uint32_t)lane * 16;
        const float4* vns = (const float4*)(smem + (size_t)s * STG + 8192);

#pragma unroll 1
        for (int kk = 0; kk < 4; kk++) {
            float4 vq[4];
#pragma unroll
            for (int j = 0; j < 4; j++) vq[j] = vns[kk * 16 + q * 4 + j];

            uint32_t HI[4][2];
#pragma unroll
            for (int ri = 0; ri < 4; ri++) {
                float d2a[4];
#pragma unroll
                for (int j = 0; j < 4; j++) {
                    float s0 = n2[ri] + vq[j].w;
                    d2a[j] = fmaf(px[ri], vq[j].x,
                             fmaf(py[ri], vq[j].y,
                             fmaf(pz[ri], vq[j].z, s0)));
                }
                HI[ri][0] = wpair(d2a[0], d2a[1]);
                HI[ri][1] = wpair(d2a[2], d2a[3]);
            }

#pragma unroll
            for (int tp = 0; tp < 4; tp++) {
                uint4 bb = lds128(lb + (uint32_t)((kk * 4 + tp) * 512));
                mma16816(acc[0][2 * tp + 0], HI[0][0], HI[1][0], HI[0][1], HI[1][1], bb.x, bb.y);
                mma16816(acc[1][2 * tp + 0], HI[2][0], HI[3][0], HI[2][1], HI[3][1], bb.x, bb.y);
                mma16816(acc[0][2 * tp + 1], HI[0][0], HI[1][0], HI[0][1], HI[1][1], bb.z, bb.w);
                mma16816(acc[1][2 * tp + 1], HI[2][0], HI[3][0], HI[2][1], HI[3][1], bb.z, bb.w);
            }
            mma16816(acc[0][8], HI[0][0], HI[1][0], HI[0][1], HI[1][1], bcst, bcst);
            mma16816(acc[1][8], HI[2][0], HI[3][0], HI[2][1], HI[3][1], bcst, bcst);
        }
        __syncthreads();
        if (ch + 2 < NCH) stage_cp(ch + 2);
    }

    // unnormalized partials + dens (dens = D column 64, lane&3==0)
#pragma unroll
    for (int ri = 0; ri < 4; ri++) {
        const size_t qq = (size_t)b * LL + rbase + ri * 8;
        float* orow = g_part + (qq * NVH + vh) * RX + side * 68;
        const int mt = ri >> 1, rp = (ri & 1) * 2;
#pragma unroll
        for (int t = 0; t < 8; t++) {
            float2 v2;
            v2.x = acc[mt][t][rp + 0];
            v2.y = acc[mt][t][rp + 1];
            *(float2*)(orow + t * 8 + q * 2) = v2;
        }
        if (q == 0) orow[64] = acc[mt][8][rp];
    }
}

// ---------------- MLP: vectorized partial gather + 130->130 relu ->1 ----------------
__global__ void __launch_bounds__(256) mlp_kernel(const float* __restrict__ b2,
                                                  float* __restrict__ out) {
    __shared__ float xs[8][4][132];
    const int warp = threadIdx.x >> 5;
    const int lane = threadIdx.x & 31;
    const int q0 = (blockIdx.x * 8 + warp) * 4;

#pragma unroll
    for (int qq = 0; qq < 4; qq++) {
        const size_t q = q0 + qq;
        const float4* pp = (const float4*)(g_part + q * (NVH * RX));  // 8 planes x 34 float4
        float4 v = make_float4(0.f, 0.f, 0.f, 0.f);
#pragma unroll
        for (int s = 0; s < NVH; s++) {
            float4 t = pp[s * 34 + lane];
            v.x += t.x; v.y += t.y; v.z += t.z; v.w += t.w;
        }
        float4 ve = make_float4(0.f, 0.f, 0.f, 0.f);
        if (lane < 2) {
#pragma unroll
            for (int s = 0; s < NVH; s++) {
                float4 t = pp[s * 34 + 32 + lane];
                ve.x += t.x; ve.y += t.y; ve.z += t.z; ve.w += t.w;
            }
        }
        const float dl = __shfl_sync(0xFFFFFFFFu, v.x, 16);   // pc=64
        const float dr = __shfl_sync(0xFFFFFFFFu, ve.x, 1);   // pc=132
        const float il = 1.f / dl, ir = 1.f / dr;
        float* xw = xs[warp][qq];
        if (lane < 16) {            // pc=4L..4L+3 -> c=pc, left side
            xw[4 * lane + 0] = v.x * il; xw[4 * lane + 1] = v.y * il;
            xw[4 * lane + 2] = v.z * il; xw[4 * lane + 3] = v.w * il;
        } else if (lane == 16) {    // pc=64 -> dens left (raw)
            xw[64] = v.x;
        } else {                    // pc=4L..4L+3 -> c=pc-3, right side (c=65..124)
            const int c = 4 * lane - 3;
            xw[c + 0] = v.x * ir; xw[c + 1] = v.y * ir;
            xw[c + 2] = v.z * ir; xw[c + 3] = v.w * ir;
        }
        if (lane == 0) {            // pc=128..131 -> c=125..128
            xw[125] = ve.x * ir; xw[126] = ve.y * ir;
            xw[127] = ve.z * ir; xw[128] = ve.w * ir;
        }
        if (lane == 1) xw[129] = ve.x;   // dens right (raw)
    }
    __syncwarp();

    const float4* wv = (const float4*)g_w1t;
    float4 hA[4], hB[4];
#pragma unroll
    for (int qq = 0; qq < 4; qq++) { hA[qq] = make_float4(0, 0, 0, 0); hB[qq] = hA[qq]; }
#pragma unroll 2
    for (int k = 0; k < 130; k++) {
        const float4 wA = wv[k * 33 + lane];
        const float4 wB = wv[k * 33 + 32];
#pragma unroll
        for (int qq = 0; qq < 4; qq++) {
            const float x = xs[warp][qq][k];
            hA[qq].x = fmaf(wA.x, x, hA[qq].x); hA[qq].y = fmaf(wA.y, x, hA[qq].y);
            hA[qq].z = fmaf(wA.z, x, hA[qq].z); hA[qq].w = fmaf(wA.w, x, hA[qq].w);
            hB[qq].x = fmaf(wB.x, x, hB[qq].x); hB[qq].y = fmaf(wB.y, x, hB[qq].y);
            hB[qq].z = fmaf(wB.z, x, hB[qq].z); hB[qq].w = fmaf(wB.w, x, hB[qq].w);
        }
    }
    const float4 b1A = ((const float4*)g_b1p)[lane];
    const float4 w2A = ((const float4*)g_w2p)[lane];
    const float4 b1B = ((const float4*)g_b1p)[32];
    const float4 w2B = ((const float4*)g_w2p)[32];
    const float bb = b2[0];

#pragma unroll
    for (int qq = 0; qq < 4; qq++) {
        float r = fmaxf(hA[qq].x + b1A.x, 0.f) * w2A.x + fmaxf(hA[qq].y + b1A.y, 0.f) * w2A.y
                + fmaxf(hA[qq].z + b1A.z, 0.f) * w2A.z + fmaxf(hA[qq].w + b1A.w, 0.f) * w2A.w;
        if (lane == 0)
            r += fmaxf(hB[qq].x + b1B.x, 0.f) * w2B.x + fmaxf(hB[qq].y + b1B.y, 0.f) * w2B.y
               + fmaxf(hB[qq].z + b1B.z, 0.f) * w2B.z + fmaxf(hB[qq].w + b1B.w, 0.f) * w2B.w;
#pragma unroll
        for (int o = 16; o > 0; o >>= 1) r += __shfl_xor_sync(0xFFFFFFFFu, r, o);
        if (lane == 0) out[q0 + qq] = r + bb;
    }
}

extern "C" void kernel_launch(void* const* d_in, const int* in_sizes, int n_in,
                              void* d_out, int out_size) {
    (void)in_sizes; (void)n_in; (void)out_size;
    const float* locsL  = (const float*)d_in[0];
    const float* locsR  = (const float*)d_in[1];
    const float* vertsL = (const float*)d_in[2];
    const float* vertsR = (const float*)d_in[3];
    const float* featsL = (const float*)d_in[4];
    const float* featsR = (const float*)d_in[5];
    const float* w1     = (const float*)d_in[6];
    const float* b1     = (const float*)d_in[7];
    const float* w2     = (const float*)d_in[8];
    const float* b2     = (const float*)d_in[9];
    float* out = (float*)d_out;

    prep_vn_kernel<<<dim3(VV / 256, 16), 256>>>(vertsL, vertsR);
    prep_feats_kernel<<<dim3(NCG, 16), 256>>>(featsL, featsR);
    prep_w1_kernel<<<69, 256>>>(w1, b1, w2);
    interp_kernel<<<dim3(LL / 128, 16, NVH), 128>>>(locsL, locsR);
    mlp_kernel<<<NQ / 32, 256>>>(b2, out);
}

// round 12
// speedup vs baseline: 1.0832x; 1.0832x over previous
#include <cuda_runtime.h>
#include <cuda_fp16.h>
#include <cstdint>

#define BB 8
#define LL 2048
#define VV 8192
#define CC 64
#define NQ (BB * LL)
#define NVH 8
#define VH (VV / NVH)        // 1024 verts per CTA
#define NCH (VH / 64)        // 16 chunks of 64 verts
#define NCG (VV / 64)        // 128 chunks globally
#define RX 136

typedef unsigned long long ull;

static __device__ float  g_part[(size_t)NVH * NQ * RX];       // [vh][q][136]
static __device__ float4 g_vn[(size_t)2 * BB * VV * 2];       // dup-packed swizzled verts
static __device__ uint2  g_fB[(size_t)2 * BB * NCG * 1024];   // frag-major fp16 B (t-paired)
static __device__ float  g_w1t[132 * 132];
static __device__ float  g_b1p[132];
static __device__ float  g_w2p[132];

__device__ __forceinline__ void cp16(uint32_t d, const void* s) {
    asm volatile("cp.async.cg.shared.global [%0], [%1], 16;" :: "r"(d), "l"(s));
}
__device__ __forceinline__ uint4 lds128(uint32_t addr) {
    uint4 r;
    asm volatile("ld.shared.v4.b32 {%0,%1,%2,%3}, [%4];"
                 : "=r"(r.x), "=r"(r.y), "=r"(r.z), "=r"(r.w) : "r"(addr));
    return r;
}
__device__ __forceinline__ void lds2u64(ull& a, ull& b, uint32_t addr) {
    asm volatile("ld.shared.v2.b64 {%0,%1}, [%2];" : "=l"(a), "=l"(b) : "r"(addr));
}
__device__ __forceinline__ ull pack2(float x, float y) {
    ull d; asm("mov.b64 %0, {%1, %2};" : "=l"(d) : "f"(x), "f"(y)); return d;
}
__device__ __forceinline__ void unpack2(ull v, float& x, float& y) {
    asm("mov.b64 {%0, %1}, %2;" : "=f"(x), "=f"(y) : "l"(v));
}
__device__ __forceinline__ ull fma2(ull a, ull b, ull c) {
    ull d; asm("fma.rn.f32x2 %0, %1, %2, %3;" : "=l"(d) : "l"(a), "l"(b), "l"(c)); return d;
}
__device__ __forceinline__ ull add2(ull a, ull b) {
    ull d; asm("add.rn.f32x2 %0, %1, %2;" : "=l"(d) : "l"(a), "l"(b)); return d;
}
__device__ __forceinline__ uint32_t packh2(float lo, float hi) {
    uint32_t r; asm("cvt.rn.f16x2.f32 %0, %1, %2;" : "=r"(r) : "f"(hi), "f"(lo)); return r;
}
__device__ __forceinline__ uint32_t ex2h2(uint32_t a) {
    uint32_t r; asm("ex2.approx.f16x2 %0, %1;" : "=r"(r) : "r"(a)); return r;
}
// w pair from two fp32 squared distances: clamp->rsqrt->d->*(-log2e/sigma)->2^x
__device__ __forceinline__ uint32_t wpair(float d2a, float d2b) {
    const __half2 minn = __halves2half2(__ushort_as_half(0x0400), __ushort_as_half(0x0400));
    const __half2 negc = __float2half2_rn(-0.57707801635558535f);
    uint32_t u = packh2(d2a, d2b);
    __half2 v = __hmax2(*(__half2*)&u, minn);
    __half2 r = h2rsqrt(v);
    __half2 d = __hmul2(v, r);
    __half2 a = __hmul2(d, negc);
    return ex2h2(*(uint32_t*)&a);
}
__device__ __forceinline__ void mma16816(float* d, uint32_t a0, uint32_t a1, uint32_t a2,
                                         uint32_t a3, uint32_t b0, uint32_t b1) {
    asm volatile(
        "mma.sync.aligned.m16n8k16.row.col.f32.f16.f16.f32 "
        "{%0,%1,%2,%3},{%4,%5,%6,%7},{%8,%9},{%0,%1,%2,%3};"
        : "+f"(d[0]), "+f"(d[1]), "+f"(d[2]), "+f"(d[3])
        : "r"(a0), "r"(a1), "r"(a2), "r"(a3), "r"(b0), "r"(b1));
}

// ---------------- preps ----------------
// dup-packed swizzled verts: vert (chunk, kk, q, j) -> float4 pair at
//   chunk*128 + kk*32 + q*8 + (j^q)*2 (float4 units)
__global__ void prep_vn_kernel(const float* __restrict__ vL, const float* __restrict__ vR) {
    const int v = blockIdx.x * 256 + threadIdx.x;
    const int bs = blockIdx.y, b = bs >> 1, side = bs & 1;
    const float* vp = (side ? vR : vL) + ((size_t)b * VV + v) * 3;
    const float x = vp[0], y = vp[1], z = vp[2];
    const float n1 = fmaf(x, x, fmaf(y, y, z * z));
    const int i = v & 15, q = i >> 2, j = i & 3;
    const size_t idx = ((size_t)bs * VV + (v & ~15)) * 2 + q * 8 + ((j ^ q) * 2);
    g_vn[idx + 0] = make_float4(-2.f * x, -2.f * x, -2.f * y, -2.f * y);
    g_vn[idx + 1] = make_float4(-2.f * z, -2.f * z, n1, n1);
}

// fragment-major, t-paired B, written dst-linear (coalesced)
__global__ void prep_feats_kernel(const float* __restrict__ fL, const float* __restrict__ fR) {
    __shared__ float tile[64][65];
    const int ci = blockIdx.x, bs = blockIdx.y, b = bs >> 1, side = bs & 1;
    const int tid = threadIdx.x;
    const float* src = (side ? fR : fL) + ((size_t)b * VV + (size_t)ci * 64) * CC;
#pragma unroll
    for (int i = 0; i < 16; i++) {
        int idx = tid + 256 * i;
        tile[idx >> 6][idx & 63] = src[idx];   // tile[v][c]
    }
    __syncthreads();
    uint2* dst = g_fB + ((size_t)bs * NCG + ci) * 1024;
#pragma unroll
    for (int i = 0; i < 4; i++) {
        int di = tid + 256 * i;                // dst-linear
        int g = di >> 6, l2 = di & 63;
        int lane = l2 >> 1, tb = l2 & 1;
        int kk = g >> 2, tp = g & 3, t = tp * 2 + tb;
        int c = t * 8 + (lane >> 2);
        int v0 = kk * 16 + (lane & 3) * 4;
        __half2 p0 = __floats2half2_rn(tile[v0 + 0][c], tile[v0 + 1][c]);
        __half2 p1 = __floats2half2_rn(tile[v0 + 2][c], tile[v0 + 3][c]);
        uint2 o; o.x = *(uint32_t*)&p0; o.y = *(uint32_t*)&p1;
        dst[di] = o;
    }
}

__global__ void prep_w1_kernel(const float* __restrict__ w1, const float* __restrict__ b1,
                               const float* __restrict__ w2) {
    const int idx = blockIdx.x * 256 + threadIdx.x;
    if (idx < 132 * 132) {
        const int k = idx / 132, j = idx % 132;
        g_w1t[idx] = (j < 130 && k < 130) ? w1[j * 130 + k] : 0.f;
    }
    if (blockIdx.x == 0 && idx < 132) {
        g_b1p[idx] = (idx < 130) ? b1[idx] : 0.f;
        g_w2p[idx] = (idx < 130) ? w2[idx] : 0.f;
    }
}

// ---------------- fused interp ----------------
// grid (LL/128, 16, NVH), block 128 (4 warps, each M=32 x N=65)
// stage: B frags @0 (8192B), vn dup-packed @8192 (2048B)
#define STG 10240

__global__ void __launch_bounds__(128, 4)
interp_kernel(const float* __restrict__ locsL, const float* __restrict__ locsR) {
    __shared__ __align__(1024) char smem[2 * STG];
    const uint32_t sb = (uint32_t)__cvta_generic_to_shared(smem);
    const int tid = threadIdx.x, lane = tid & 31, warp = tid >> 5;
    const int lt = blockIdx.x, bs = blockIdx.y, vh = blockIdx.z;
    const int b = bs >> 1, side = bs & 1;

    const float* locs = (side ? locsR : locsL) + (size_t)b * LL * 3;
    const int rbase = lt * 128 + warp * 32 + (lane >> 2);
    ull pxp[2], pyp[2], pzp[2], n2p[2];
    {
        float px[4], py[4], pz[4], n2[4];
#pragma unroll
        for (int ri = 0; ri < 4; ri++) {
            const float* p = locs + (size_t)(rbase + ri * 8) * 3;
            px[ri] = p[0]; py[ri] = p[1]; pz[ri] = p[2];
            n2[ri] = fmaf(px[ri], px[ri], fmaf(py[ri], py[ri], pz[ri] * pz[ri]));
        }
#pragma unroll
        for (int rp = 0; rp < 2; rp++) {
            pxp[rp] = pack2(px[2 * rp], px[2 * rp + 1]);
            pyp[rp] = pack2(py[2 * rp], py[2 * rp + 1]);
            pzp[rp] = pack2(pz[2 * rp], pz[2 * rp + 1]);
            n2p[rp] = pack2(n2[2 * rp], n2[2 * rp + 1]);
        }
    }
    const uint2*  fbb = g_fB + ((size_t)bs * NCG + vh * NCH) * 1024;
    const float4* vnb = g_vn + ((size_t)bs * VV + vh * VH) * 2;

    // t=8 constant B fragment (dens column: channel 64 = ones, 65..71 zero)
    const uint32_t bcst = ((lane >> 2) == 0) ? 0x3C003C00u : 0u;

    float acc[2][9][4];
#pragma unroll
    for (int m = 0; m < 2; m++)
#pragma unroll
        for (int t = 0; t < 9; t++)
#pragma unroll
            for (int i = 0; i < 4; i++) acc[m][t][i] = 0.f;

    auto stage_cp = [&](int ch) {
        const uint32_t dst = sb + (uint32_t)(ch & 1) * STG;
        const char* src = (const char*)(fbb + (size_t)ch * 1024);
#pragma unroll
        for (int i = 0; i < 4; i++)
            cp16(dst + (tid + i * 128) * 16, src + (tid + i * 128) * 16);
        cp16(dst + 8192 + tid * 16, vnb + (size_t)ch * 128 + tid);
        asm volatile("cp.async.commit_group;");
    };

    stage_cp(0);
    stage_cp(1);

    const int q = lane & 3;

    for (int ch = 0; ch < NCH; ch++) {
        const int s = ch & 1;
        if (ch == NCH - 1) asm volatile("cp.async.wait_group 0;");
        else               asm volatile("cp.async.wait_group 1;");
        __syncthreads();

        const uint32_t lb = sb + (uint32_t)s * STG + (uint32_t)lane * 16;
        const uint32_t vbase = sb + (uint32_t)s * STG + 8192 + (uint32_t)q * 128;

#pragma unroll 1
        for (int kk = 0; kk < 4; kk++) {
            ull d2p[2][4];
#pragma unroll
            for (int j = 0; j < 4; j++) {
                const uint32_t ad = vbase + (uint32_t)(kk * 512 + ((j ^ q) * 32));
                ull xd, yd, zd, wd;
                lds2u64(xd, yd, ad);
                lds2u64(zd, wd, ad + 16);
#pragma unroll
                for (int rp = 0; rp < 2; rp++)
                    d2p[rp][j] = fma2(pxp[rp], xd,
                                 fma2(pyp[rp], yd,
                                 fma2(pzp[rp], zd, add2(n2p[rp], wd))));
            }
            uint32_t HI[4][2];
#pragma unroll
            for (int rp = 0; rp < 2; rp++)
#pragma unroll
                for (int hp = 0; hp < 2; hp++) {
                    float l0, h0, l1, h1;
                    unpack2(d2p[rp][2 * hp + 0], l0, h0);
                    unpack2(d2p[rp][2 * hp + 1], l1, h1);
                    HI[2 * rp + 0][hp] = wpair(l0, l1);
                    HI[2 * rp + 1][hp] = wpair(h0, h1);
                }

#pragma unroll
            for (int tp = 0; tp < 4; tp++) {
                uint4 bb = lds128(lb + (uint32_t)((kk * 4 + tp) * 512));
                mma16816(acc[0][2 * tp + 0], HI[0][0], HI[1][0], HI[0][1], HI[1][1], bb.x, bb.y);
                mma16816(acc[1][2 * tp + 0], HI[2][0], HI[3][0], HI[2][1], HI[3][1], bb.x, bb.y);
                mma16816(acc[0][2 * tp + 1], HI[0][0], HI[1][0], HI[0][1], HI[1][1], bb.z, bb.w);
                mma16816(acc[1][2 * tp + 1], HI[2][0], HI[3][0], HI[2][1], HI[3][1], bb.z, bb.w);
            }
            mma16816(acc[0][8], HI[0][0], HI[1][0], HI[0][1], HI[1][1], bcst, bcst);
            mma16816(acc[1][8], HI[2][0], HI[3][0], HI[2][1], HI[3][1], bcst, bcst);
        }
        __syncthreads();
        if (ch + 2 < NCH) stage_cp(ch + 2);
    }

    // unnormalized partials + dens (dens = D column 64, lane&3==0)
#pragma unroll
    for (int ri = 0; ri < 4; ri++) {
        const size_t qq = (size_t)b * LL + rbase + ri * 8;
        float* orow = g_part + ((size_t)vh * NQ + qq) * RX + side * 68;
        const int mt = ri >> 1, rp = (ri & 1) * 2;
#pragma unroll
        for (int t = 0; t < 8; t++) {
            float2 v2;
            v2.x = acc[mt][t][rp + 0];
            v2.y = acc[mt][t][rp + 1];
            *(float2*)(orow + t * 8 + q * 2) = v2;
        }
        if (q == 0) orow[64] = acc[mt][8][rp];
    }
}

// ---------------- MLP (R10 known-good) ----------------
__global__ void __launch_bounds__(256) mlp_kernel(const float* __restrict__ b2,
                                                  float* __restrict__ out) {
    __shared__ float xs[8][4][132];
    const int warp = threadIdx.x >> 5;
    const int lane = threadIdx.x & 31;
    const int q0 = (blockIdx.x * 8 + warp) * 4;

#pragma unroll
    for (int qq = 0; qq < 4; qq++) {
        const size_t q = q0 + qq;
        float v[5];
#pragma unroll
        for (int m = 0; m < 5; m++) {
            const int c = lane + 32 * m;
            float sum = 0.f;
            if (c < 130) {
                const int pc = c < 65 ? c : c + 3;
#pragma unroll
                for (int s = 0; s < NVH; s++)
                    sum += g_part[((size_t)s * NQ + q) * RX + pc];
            }
            v[m] = sum;
        }
        const float dl = __shfl_sync(0xFFFFFFFFu, v[2], 0);
        const float dr = __shfl_sync(0xFFFFFFFFu, v[4], 1);
        const float il = 1.f / dl, ir = 1.f / dr;
#pragma unroll
        for (int m = 0; m < 5; m++) {
            const int c = lane + 32 * m;
            if (c < 64)        xs[warp][qq][c] = v[m] * il;
            else if (c == 64)  xs[warp][qq][64] = dl;
            else if (c < 129)  xs[warp][qq][c] = v[m] * ir;
            else if (c == 129) xs[warp][qq][129] = dr;
        }
    }
    __syncwarp();

    const float4* wv = (const float4*)g_w1t;
    float4 hA[4], hB[4];
#pragma unroll
    for (int qq = 0; qq < 4; qq++) { hA[qq] = make_float4(0, 0, 0, 0); hB[qq] = hA[qq]; }
#pragma unroll 2
    for (int k = 0; k < 130; k++) {
        const float4 wA = wv[k * 33 + lane];
        const float4 wB = wv[k * 33 + 32];
#pragma unroll
        for (int qq = 0; qq < 4; qq++) {
            const float x = xs[warp][qq][k];
            hA[qq].x = fmaf(wA.x, x, hA[qq].x); hA[qq].y = fmaf(wA.y, x, hA[qq].y);
            hA[qq].z = fmaf(wA.z, x, hA[qq].z); hA[qq].w = fmaf(wA.w, x, hA[qq].w);
            hB[qq].x = fmaf(wB.x, x, hB[qq].x); hB[qq].y = fmaf(wB.y, x, hB[qq].y);
            hB[qq].z = fmaf(wB.z, x, hB[qq].z); hB[qq].w = fmaf(wB.w, x, hB[qq].w);
        }
    }
    const float4 b1A = ((const float4*)g_b1p)[lane];
    const float4 w2A = ((const float4*)g_w2p)[lane];
    const float4 b1B = ((const float4*)g_b1p)[32];
    const float4 w2B = ((const float4*)g_w2p)[32];
    const float bb = b2[0];

#pragma unroll
    for (int qq = 0; qq < 4; qq++) {
        float r = fmaxf(hA[qq].x + b1A.x, 0.f) * w2A.x + fmaxf(hA[qq].y + b1A.y, 0.f) * w2A.y
                + fmaxf(hA[qq].z + b1A.z, 0.f) * w2A.z + fmaxf(hA[qq].w + b1A.w, 0.f) * w2A.w;
        if (lane == 0)
            r += fmaxf(hB[qq].x + b1B.x, 0.f) * w2B.x + fmaxf(hB[qq].y + b1B.y, 0.f) * w2B.y
               + fmaxf(hB[qq].z + b1B.z, 0.f) * w2B.z + fmaxf(hB[qq].w + b1B.w, 0.f) * w2B.w;
#pragma unroll
        for (int o = 16; o > 0; o >>= 1) r += __shfl_xor_sync(0xFFFFFFFFu, r, o);
        if (lane == 0) out[q0 + qq] = r + bb;
    }
}

extern "C" void kernel_launch(void* const* d_in, const int* in_sizes, int n_in,
                              void* d_out, int out_size) {
    (void)in_sizes; (void)n_in; (void)out_size;
    const float* locsL  = (const float*)d_in[0];
    const float* locsR  = (const float*)d_in[1];
    const float* vertsL = (const float*)d_in[2];
    const float* vertsR = (const float*)d_in[3];
    const float* featsL = (const float*)d_in[4];
    const float* featsR = (const float*)d_in[5];
    const float* w1     = (const float*)d_in[6];
    const float* b1     = (const float*)d_in[7];
    const float* w2     = (const float*)d_in[8];
    const float* b2     = (const float*)d_in[9];
    float* out = (float*)d_out;

    prep_vn_kernel<<<dim3(VV / 256, 16), 256>>>(vertsL, vertsR);
    prep_feats_kernel<<<dim3(NCG, 16), 256>>>(featsL, featsR);
    prep_w1_kernel<<<69, 256>>>(w1, b1, w2);
    interp_kernel<<<dim3(LL / 128, 16, NVH), 128>>>(locsL, locsR);
    mlp_kernel<<<NQ / 32, 256>>>(b2, out);
}

// round 13
// speedup vs baseline: 1.0930x; 1.0091x over previous
#include <cuda_runtime.h>
#include <cuda_fp16.h>
#include <cstdint>

#define BB 8
#define LL 2048
#define VV 8192
#define CC 64
#define NQ (BB * LL)
#define NVH 8
#define VH (VV / NVH)        // 1024 verts per CTA
#define NCH (VH / 64)        // 16 chunks of 64 verts
#define NCG (VV / 64)        // 128 chunks globally
#define RX 136

typedef unsigned long long ull;

static __device__ float  g_part[(size_t)NVH * NQ * RX];       // [vh][q][136]
static __device__ float4 g_vn[(size_t)2 * BB * VV * 2];       // dup-packed swizzled verts
static __device__ uint2  g_fB[(size_t)2 * BB * NCG * 1024];   // frag-major fp16 B (t-paired)
static __device__ float  g_w1t[132 * 132];
static __device__ float  g_b1p[132];
static __device__ float  g_w2p[132];

__device__ __forceinline__ void cp16(uint32_t d, const void* s) {
    asm volatile("cp.async.cg.shared.global [%0], [%1], 16;" :: "r"(d), "l"(s));
}
__device__ __forceinline__ uint4 lds128(uint32_t addr) {
    uint4 r;
    asm volatile("ld.shared.v4.b32 {%0,%1,%2,%3}, [%4];"
                 : "=r"(r.x), "=r"(r.y), "=r"(r.z), "=r"(r.w) : "r"(addr));
    return r;
}
__device__ __forceinline__ void lds2u64(ull& a, ull& b, uint32_t addr) {
    asm volatile("ld.shared.v2.b64 {%0,%1}, [%2];" : "=l"(a), "=l"(b) : "r"(addr));
}
__device__ __forceinline__ ull pack2(float x, float y) {
    ull d; asm("mov.b64 %0, {%1, %2};" : "=l"(d) : "f"(x), "f"(y)); return d;
}
__device__ __forceinline__ void unpack2(ull v, float& x, float& y) {
    asm("mov.b64 {%0, %1}, %2;" : "=f"(x), "=f"(y) : "l"(v));
}
__device__ __forceinline__ ull fma2(ull a, ull b, ull c) {
    ull d; asm("fma.rn.f32x2 %0, %1, %2, %3;" : "=l"(d) : "l"(a), "l"(b), "l"(c)); return d;
}
__device__ __forceinline__ ull add2(ull a, ull b) {
    ull d; asm("add.rn.f32x2 %0, %1, %2;" : "=l"(d) : "l"(a), "l"(b)); return d;
}
__device__ __forceinline__ uint32_t packh2(float lo, float hi) {
    uint32_t r; asm("cvt.rn.f16x2.f32 %0, %1, %2;" : "=r"(r) : "f"(hi), "f"(lo)); return r;
}
__device__ __forceinline__ uint32_t ex2h2(uint32_t a) {
    uint32_t r; asm("ex2.approx.f16x2 %0, %1;" : "=r"(r) : "r"(a)); return r;
}
// w pair from two fp32 squared distances: clamp->rsqrt->d->*(-log2e/sigma)->2^x
__device__ __forceinline__ uint32_t wpair(float d2a, float d2b) {
    const __half2 minn = __halves2half2(__ushort_as_half(0x0400), __ushort_as_half(0x0400));
    const __half2 negc = __float2half2_rn(-0.57707801635558535f);
    uint32_t u = packh2(d2a, d2b);
    __half2 v = __hmax2(*(__half2*)&u, minn);
    __half2 r = h2rsqrt(v);
    __half2 d = __hmul2(v, r);
    __half2 a = __hmul2(d, negc);
    return ex2h2(*(uint32_t*)&a);
}
__device__ __forceinline__ void mma16816(float* d, uint32_t a0, uint32_t a1, uint32_t a2,
                                         uint32_t a3, uint32_t b0, uint32_t b1) {
    asm volatile(
        "mma.sync.aligned.m16n8k16.row.col.f32.f16.f16.f32 "
        "{%0,%1,%2,%3},{%4,%5,%6,%7},{%8,%9},{%0,%1,%2,%3};"
        : "+f"(d[0]), "+f"(d[1]), "+f"(d[2]), "+f"(d[3])
        : "r"(a0), "r"(a1), "r"(a2), "r"(a3), "r"(b0), "r"(b1));
}

// ---------------- preps ----------------
// dup-packed swizzled verts: vert (chunk, kk, q, j) -> float4 pair at
//   chunk*128 + kk*32 + q*8 + (j^q)*2 (float4 units)
__global__ void prep_vn_kernel(const float* __restrict__ vL, const float* __restrict__ vR) {
    const int v = blockIdx.x * 256 + threadIdx.x;
    const int bs = blockIdx.y, b = bs >> 1, side = bs & 1;
    const float* vp = (side ? vR : vL) + ((size_t)b * VV + v) * 3;
    const float x = vp[0], y = vp[1], z = vp[2];
    const float n1 = fmaf(x, x, fmaf(y, y, z * z));
    const int i = v & 15, q = i >> 2, j = i & 3;
    const size_t idx = ((size_t)bs * VV + (v & ~15)) * 2 + q * 8 + ((j ^ q) * 2);
    g_vn[idx + 0] = make_float4(-2.f * x, -2.f * x, -2.f * y, -2.f * y);
    g_vn[idx + 1] = make_float4(-2.f * z, -2.f * z, n1, n1);
}

// fragment-major, t-paired B, written dst-linear (coalesced)
__global__ void prep_feats_kernel(const float* __restrict__ fL, const float* __restrict__ fR) {
    __shared__ float tile[64][65];
    const int ci = blockIdx.x, bs = blockIdx.y, b = bs >> 1, side = bs & 1;
    const int tid = threadIdx.x;
    const float* src = (side ? fR : fL) + ((size_t)b * VV + (size_t)ci * 64) * CC;
#pragma unroll
    for (int i = 0; i < 16; i++) {
        int idx = tid + 256 * i;
        tile[idx >> 6][idx & 63] = src[idx];   // tile[v][c]
    }
    __syncthreads();
    uint2* dst = g_fB + ((size_t)bs * NCG + ci) * 1024;
#pragma unroll
    for (int i = 0; i < 4; i++) {
        int di = tid + 256 * i;                // dst-linear
        int g = di >> 6, l2 = di & 63;
        int lane = l2 >> 1, tb = l2 & 1;
        int kk = g >> 2, tp = g & 3, t = tp * 2 + tb;
        int c = t * 8 + (lane >> 2);
        int v0 = kk * 16 + (lane & 3) * 4;
        __half2 p0 = __floats2half2_rn(tile[v0 + 0][c], tile[v0 + 1][c]);
        __half2 p1 = __floats2half2_rn(tile[v0 + 2][c], tile[v0 + 3][c]);
        uint2 o; o.x = *(uint32_t*)&p0; o.y = *(uint32_t*)&p1;
        dst[di] = o;
    }
}

__global__ void prep_w1_kernel(const float* __restrict__ w1, const float* __restrict__ b1,
                               const float* __restrict__ w2) {
    const int idx = blockIdx.x * 256 + threadIdx.x;
    if (idx < 132 * 132) {
        const int k = idx / 132, j = idx % 132;
        g_w1t[idx] = (j < 130 && k < 130) ? w1[j * 130 + k] : 0.f;
    }
    if (blockIdx.x == 0 && idx < 132) {
        g_b1p[idx] = (idx < 130) ? b1[idx] : 0.f;
        g_w2p[idx] = (idx < 130) ? w2[idx] : 0.f;
    }
}

// ---------------- fused interp ----------------
// grid (LL/128, 16, NVH), block 128 (4 warps, each M=32 x N=65)
// 4-stage ring; stage: B frags @0 (8192B), vn dup-packed @8192 (2048B)
#define STG 10240

__global__ void __launch_bounds__(128, 4)
interp_kernel(const float* __restrict__ locsL, const float* __restrict__ locsR) {
    __shared__ __align__(1024) char smem[4 * STG];
    const uint32_t sb = (uint32_t)__cvta_generic_to_shared(smem);
    const int tid = threadIdx.x, lane = tid & 31, warp = tid >> 5;
    const int lt = blockIdx.x, bs = blockIdx.y, vh = blockIdx.z;
    const int b = bs >> 1, side = bs & 1;

    const float* locs = (side ? locsR : locsL) + (size_t)b * LL * 3;
    const int rbase = lt * 128 + warp * 32 + (lane >> 2);
    ull pxp[2], pyp[2], pzp[2], n2p[2];
    {
        float px[4], py[4], pz[4], n2[4];
#pragma unroll
        for (int ri = 0; ri < 4; ri++) {
            const float* p = locs + (size_t)(rbase + ri * 8) * 3;
            px[ri] = p[0]; py[ri] = p[1]; pz[ri] = p[2];
            n2[ri] = fmaf(px[ri], px[ri], fmaf(py[ri], py[ri], pz[ri] * pz[ri]));
        }
#pragma unroll
        for (int rp = 0; rp < 2; rp++) {
            pxp[rp] = pack2(px[2 * rp], px[2 * rp + 1]);
            pyp[rp] = pack2(py[2 * rp], py[2 * rp + 1]);
            pzp[rp] = pack2(pz[2 * rp], pz[2 * rp + 1]);
            n2p[rp] = pack2(n2[2 * rp], n2[2 * rp + 1]);
        }
    }
    const uint2*  fbb = g_fB + ((size_t)bs * NCG + vh * NCH) * 1024;
    const float4* vnb = g_vn + ((size_t)bs * VV + vh * VH) * 2;

    // t=8 constant B fragment (dens column: channel 64 = ones, 65..71 zero)
    const uint32_t bcst = ((lane >> 2) == 0) ? 0x3C003C00u : 0u;

    float acc[2][9][4];
#pragma unroll
    for (int m = 0; m < 2; m++)
#pragma unroll
        for (int t = 0; t < 9; t++)
#pragma unroll
            for (int i = 0; i < 4; i++) acc[m][t][i] = 0.f;

    auto stage_cp = [&](int ch) {
        if (ch < NCH) {
            const uint32_t dst = sb + (uint32_t)(ch & 3) * STG;
            const char* src = (const char*)(fbb + (size_t)ch * 1024);
#pragma unroll
            for (int i = 0; i < 4; i++)
                cp16(dst + (tid + i * 128) * 16, src + (tid + i * 128) * 16);
            cp16(dst + 8192 + tid * 16, vnb + (size_t)ch * 128 + tid);
        }
        asm volatile("cp.async.commit_group;");
    };

    stage_cp(0);
    stage_cp(1);
    stage_cp(2);

    const int q = lane & 3;

    for (int ch = 0; ch < NCH; ch++) {
        asm volatile("cp.async.wait_group 2;");
        __syncthreads();
        stage_cp(ch + 3);

        const uint32_t sB = sb + (uint32_t)(ch & 3) * STG;
        const uint32_t lb = sB + (uint32_t)lane * 16;
        const uint32_t vbase = sB + 8192 + (uint32_t)q * 128;

#pragma unroll 1
        for (int kk = 0; kk < 4; kk++) {
            ull d2p[2][4];
#pragma unroll
            for (int j = 0; j < 4; j++) {
                const uint32_t ad = vbase + (uint32_t)(kk * 512 + ((j ^ q) * 32));
                ull xd, yd, zd, wd;
                lds2u64(xd, yd, ad);
                lds2u64(zd, wd, ad + 16);
#pragma unroll
                for (int rp = 0; rp < 2; rp++)
                    d2p[rp][j] = fma2(pxp[rp], xd,
                                 fma2(pyp[rp], yd,
                                 fma2(pzp[rp], zd, add2(n2p[rp], wd))));
            }
            uint32_t HI[4][2];
#pragma unroll
            for (int rp = 0; rp < 2; rp++)
#pragma unroll
                for (int hp = 0; hp < 2; hp++) {
                    float l0, h0, l1, h1;
                    unpack2(d2p[rp][2 * hp + 0], l0, h0);
                    unpack2(d2p[rp][2 * hp + 1], l1, h1);
                    HI[2 * rp + 0][hp] = wpair(l0, l1);
                    HI[2 * rp + 1][hp] = wpair(h0, h1);
                }

#pragma unroll
            for (int tp = 0; tp < 4; tp++) {
                uint4 bb = lds128(lb + (uint32_t)((kk * 4 + tp) * 512));
                mma16816(acc[0][2 * tp + 0], HI[0][0], HI[1][0], HI[0][1], HI[1][1], bb.x, bb.y);
                mma16816(acc[1][2 * tp + 0], HI[2][0], HI[3][0], HI[2][1], HI[3][1], bb.x, bb.y);
                mma16816(acc[0][2 * tp + 1], HI[0][0], HI[1][0], HI[0][1], HI[1][1], bb.z, bb.w);
                mma16816(acc[1][2 * tp + 1], HI[2][0], HI[3][0], HI[2][1], HI[3][1], bb.z, bb.w);
            }
            mma16816(acc[0][8], HI[0][0], HI[1][0], HI[0][1], HI[1][1], bcst, bcst);
            mma16816(acc[1][8], HI[2][0], HI[3][0], HI[2][1], HI[3][1], bcst, bcst);
        }
    }

    // unnormalized partials + dens (dens = D column 64, lane&3==0)
#pragma unroll
    for (int ri = 0; ri < 4; ri++) {
        const size_t qq = (size_t)b * LL + rbase + ri * 8;
        float* orow = g_part + ((size_t)vh * NQ + qq) * RX + side * 68;
        const int mt = ri >> 1, rp = (ri & 1) * 2;
#pragma unroll
        for (int t = 0; t < 8; t++) {
            float2 v2;
            v2.x = acc[mt][t][rp + 0];
            v2.y = acc[mt][t][rp + 1];
            *(float2*)(orow + t * 8 + q * 2) = v2;
        }
        if (q == 0) orow[64] = acc[mt][8][rp];
    }
}

// ---------------- MLP: float4 gather + lean 130->130 relu ->1 ----------------
// lane owns j = 4*lane..4*lane+3 (0..127); lanes 0,1 carry j=128,129.
__global__ void __launch_bounds__(256) mlp_kernel(const float* __restrict__ b2,
                                                  float* __restrict__ out) {
    __shared__ float xs[8][4][132];
    const int warp = threadIdx.x >> 5;
    const int lane = threadIdx.x & 31;
    const int q0 = (blockIdx.x * 8 + warp) * 4;

#pragma unroll
    for (int qq = 0; qq < 4; qq++) {
        const size_t q = q0 + qq;
        float4 v = make_float4(0.f, 0.f, 0.f, 0.f);
#pragma unroll
        for (int s = 0; s < NVH; s++) {
            float4 t = ((const float4*)(g_part + ((size_t)s * NQ + q) * RX))[lane];
            v.x += t.x; v.y += t.y; v.z += t.z; v.w += t.w;
        }
        float4 ve = make_float4(0.f, 0.f, 0.f, 0.f);
        if (lane < 2) {
#pragma unroll
            for (int s = 0; s < NVH; s++) {
                float4 t = ((const float4*)(g_part + ((size_t)s * NQ + q) * RX))[32 + lane];
                ve.x += t.x; ve.y += t.y; ve.z += t.z; ve.w += t.w;
            }
        }
        const float dl = __shfl_sync(0xFFFFFFFFu, v.x, 16);   // pc=64
        const float dr = __shfl_sync(0xFFFFFFFFu, ve.x, 1);   // pc=132
        const float il = 1.f / dl, ir = 1.f / dr;
        float* xw = xs[warp][qq];
        if (lane < 16) {            // pc=4L..4L+3 -> c=pc (left feats)
            xw[4 * lane + 0] = v.x * il; xw[4 * lane + 1] = v.y * il;
            xw[4 * lane + 2] = v.z * il; xw[4 * lane + 3] = v.w * il;
        } else if (lane == 16) {    // pc=64 -> dens left (raw)
            xw[64] = v.x;
        } else {                    // pc=4L..4L+3 (68..127) -> c=pc-3 (65..124)
            const int c = 4 * lane - 3;
            xw[c + 0] = v.x * ir; xw[c + 1] = v.y * ir;
            xw[c + 2] = v.z * ir; xw[c + 3] = v.w * ir;
        }
        if (lane == 0) {            // pc=128..131 -> c=125..128
            xw[125] = ve.x * ir; xw[126] = ve.y * ir;
            xw[127] = ve.z * ir; xw[128] = ve.w * ir;
        }
        if (lane == 1) xw[129] = ve.x;   // pc=132 -> dens right (raw)
    }
    __syncwarp();

    const float4* wv = (const float4*)g_w1t;
    float4 hA[4];
    float  hE[4];
#pragma unroll
    for (int qq = 0; qq < 4; qq++) { hA[qq] = make_float4(0, 0, 0, 0); hE[qq] = 0.f; }
#pragma unroll 2
    for (int k = 0; k < 130; k++) {
        const float4 wA = wv[k * 33 + lane];
        const float  wE = (lane < 2) ? g_w1t[k * 132 + 128 + lane] : 0.f;
#pragma unroll
        for (int qq = 0; qq < 4; qq++) {
            const float x = xs[warp][qq][k];
            hA[qq].x = fmaf(wA.x, x, hA[qq].x); hA[qq].y = fmaf(wA.y, x, hA[qq].y);
            hA[qq].z = fmaf(wA.z, x, hA[qq].z); hA[qq].w = fmaf(wA.w, x, hA[qq].w);
            hE[qq]   = fmaf(wE,   x, hE[qq]);
        }
    }
    const float4 b1A = ((const float4*)g_b1p)[lane];
    const float4 w2A = ((const float4*)g_w2p)[lane];
    const float  b1E = (lane < 2) ? g_b1p[128 + lane] : 0.f;
    const float  w2E = (lane < 2) ? g_w2p[128 + lane] : 0.f;
    const float bb = b2[0];

#pragma unroll
    for (int qq = 0; qq < 4; qq++) {
        float r = fmaxf(hA[qq].x + b1A.x, 0.f) * w2A.x + fmaxf(hA[qq].y + b1A.y, 0.f) * w2A.y
                + fmaxf(hA[qq].z + b1A.z, 0.f) * w2A.z + fmaxf(hA[qq].w + b1A.w, 0.f) * w2A.w;
        if (lane < 2)
            r += fmaxf(hE[qq] + b1E, 0.f) * w2E;
#pragma unroll
        for (int o = 16; o > 0; o >>= 1) r += __shfl_xor_sync(0xFFFFFFFFu, r, o);
        if (lane == 0) out[q0 + qq] = r + bb;
    }
}

extern "C" void kernel_launch(void* const* d_in, const int* in_sizes, int n_in,
                              void* d_out, int out_size) {
    (void)in_sizes; (void)n_in; (void)out_size;
    const float* locsL  = (const float*)d_in[0];
    const float* locsR  = (const float*)d_in[1];
    const float* vertsL = (const float*)d_in[2];
    const float* vertsR = (const float*)d_in[3];
    const float* featsL = (const float*)d_in[4];
    const float* featsR = (const float*)d_in[5];
    const float* w1     = (const float*)d_in[6];
    const float* b1     = (const float*)d_in[7];
    const float* w2     = (const float*)d_in[8];
    const float* b2     = (const float*)d_in[9];
    float* out = (float*)d_out;

    prep_vn_kernel<<<dim3(VV / 256, 16), 256>>>(vertsL, vertsR);
    prep_feats_kernel<<<dim3(NCG, 16), 256>>>(featsL, featsR);
    prep_w1_kernel<<<69, 256>>>(w1, b1, w2);
    interp_kernel<<<dim3(LL / 128, 16, NVH), 128>>>(locsL, locsR);
    mlp_kernel<<<NQ / 32, 256>>>(b2, out);
}